// round 11
// baseline (speedup 1.0000x reference)
#include <cuda_runtime.h>
#include <cuda_fp16.h>
#include <cstdint>
#include <math.h>

#define BSZ 8192
#define NK  2048
#define BM  128
#define BN  128
#define BKF 64                     // fp32 K consumed per mainloop iteration
#define TILE_B 16384               // 128 rows x 64 fp16 = 16KB (128B rows)
#define STAGE_B (2*TILE_B)         // A, B = 32KB
#define NSTAGE 3
#define SMEM_BYTES (NSTAGE*STAGE_B)   // 96KB -> 2 CTAs/SM
#define NTHR 128                   // 4 warps, 2x2 grid of 64x64 warp tiles

// ---------------- scratch (static device globals; no runtime alloc) ----------------
__device__ __half g_xh[(size_t)BSZ*NK];
__device__ __half g_hh[(size_t)BSZ*NK];
__device__ __half g_wh[(size_t)6*NK*NK];   // [w][N][K] transposed
__device__ __half g_rh[(size_t)BSZ*NK];
__device__ float  g_Z [(size_t)BSZ*NK];

// ---------------- helpers ----------------
__device__ __forceinline__ uint32_t smem_u32(const void* p) {
    uint32_t a;
    asm("{ .reg .u64 t; cvta.to.shared.u64 t, %1; cvt.u32.u64 %0, t; }" : "=r"(a) : "l"(p));
    return a;
}
__device__ __forceinline__ void cp16(uint32_t dst, const char* src) {
    asm volatile("cp.async.cg.shared.global [%0], [%1], 16;"
                 :: "r"(dst), "l"(src) : "memory");
}
#define CP_COMMIT() asm volatile("cp.async.commit_group;" ::: "memory")
#define CP_WAIT(n)  asm volatile("cp.async.wait_group %0;" :: "n"(n) : "memory")

__device__ __forceinline__ void ldm4(uint32_t* r, uint32_t addr) {
    asm volatile("ldmatrix.sync.aligned.m8n8.x4.shared.b16 {%0,%1,%2,%3}, [%4];"
                 : "=r"(r[0]), "=r"(r[1]), "=r"(r[2]), "=r"(r[3]) : "r"(addr));
}
__device__ __forceinline__ void mma16816(float* d, const uint32_t* a,
                                         uint32_t b0, uint32_t b1) {
    asm volatile(
        "mma.sync.aligned.m16n8k16.row.col.f32.f16.f16.f32 "
        "{%0,%1,%2,%3}, {%4,%5,%6,%7}, {%8,%9}, {%0,%1,%2,%3};"
        : "+f"(d[0]), "+f"(d[1]), "+f"(d[2]), "+f"(d[3])
        : "r"(a[0]), "r"(a[1]), "r"(a[2]), "r"(a[3]), "r"(b0), "r"(b1));
}
__device__ __forceinline__ float sigf(float x) { return 1.0f / (1.0f + __expf(-x)); }

__device__ __forceinline__ uint32_t pack_h2(float a, float b) {
    __half2 h = __floats2half2_rn(a, b);
    return *(uint32_t*)&h;
}

// Swizzled byte address inside a 128x64-fp16 tile (128B per row, SW128).
// row: 0..127, c: 16B-chunk index within row (0..7).
__device__ __forceinline__ uint32_t swz(uint32_t row, uint32_t c) {
    return row * 128 + ((c ^ (row & 7)) << 4);
}

// ---------------- prep: convert x and h to fp16 (one kernel) ----------------
__global__ void cvt_half(const float4* __restrict__ xin, const float4* __restrict__ hin) {
    size_t i = (size_t)blockIdx.x * 256 + threadIdx.x;   // BSZ*NK/4 threads per plane
    int which = blockIdx.y;
    const float4* in = which ? hin : xin;
    uint2* dst = (uint2*)(which ? g_hh : g_xh);
    float4 v = in[i];
    dst[i] = make_uint2(pack_h2(v.x, v.y), pack_h2(v.z, v.w));
}

// ---------------- prep: transpose + convert all 6 weights ----------------
__global__ void wt_cvt(const float* __restrict__ W0, const float* __restrict__ W1,
                       const float* __restrict__ W2, const float* __restrict__ W3,
                       const float* __restrict__ W4, const float* __restrict__ W5) {
    __shared__ float t[32][33];
    int w = blockIdx.z;
    const float* src = (w == 0) ? W0 : (w == 1) ? W1 : (w == 2) ? W2
                     : (w == 3) ? W3 : (w == 4) ? W4 : W5;
    int nt = blockIdx.x * 32, kt = blockIdx.y * 32;
    int tx = threadIdx.x & 31, ty = threadIdx.x >> 5;
    #pragma unroll
    for (int j = 0; j < 4; j++) {
        int r = ty + j * 8;
        t[r][tx] = src[(size_t)(kt + r) * NK + nt + tx];
    }
    __syncthreads();
    size_t wbase = (size_t)w * NK * NK;
    #pragma unroll
    for (int j = 0; j < 4; j++) {
        int r = ty + j * 8;
        g_wh[wbase + (size_t)(nt + r) * NK + kt + tx] = __float2half_rn(t[tx][r]);
    }
}

// ---------------- fp16 mma.sync mainloop (shared by both stages) ----------------
// acc += A[m0:m0+128, :] @ B[ncol:ncol+128, :]^T over `iters` chunks of 64
// fp32-K each; switches to operand set 2 at iter 32 (two-pass when iters=64).
// 4 warps, 2x2 grid of 64x64 warp tiles.
__device__ __forceinline__ void gemm_mainloop(
    const __half* a1, const __half* b1,
    const __half* a2, const __half* b2,
    int iters, int m0, int ncol, uint32_t smem,
    float (&acc)[4][8][4])
{
    const int tid  = threadIdx.x;
    const int lane = tid & 31;
    const int wid  = tid >> 5;
    const int wm   = wid >> 1;     // 0..1
    const int wn   = wid & 1;      // 0..1

    // --- cp.async write addressing: 8 chunks per 16KB tile per thread ---
    // j-step = +16 rows => row&7 unchanged => address step is a constant.
    const uint32_t row0 = (uint32_t)tid >> 3;     // 0..15
    const uint32_t cch  = (uint32_t)tid & 7;
    const uint32_t swr0  = swz(row0, cch);
    const uint32_t offM0 = ((uint32_t)(m0 + row0) * NK + cch * 8) * 2;
    const uint32_t offN0 = ((uint32_t)(ncol + row0) * NK + cch * 8) * 2;

    auto loads = [&](int L, uint32_t sb) {
        bool p2 = (L >= 32);
        const char* ap = (const char*)(p2 ? a2 : a1);
        const char* bp = (const char*)(p2 ? b2 : b1);
        uint32_t kk = ((uint32_t)L & 31u) * (BKF * 2);     // byte offset in K
        #pragma unroll
        for (int j = 0; j < 8; j++) {
            uint32_t sw = swr0 + (uint32_t)j * 16u * 128u;
            uint32_t go = (uint32_t)j * 16u * NK * 2u + kk;
            cp16(sb +          sw, ap + offM0 + go);
            cp16(sb + TILE_B + sw, bp + offN0 + go);
        }
        CP_COMMIT();
    };

    // --- ldmatrix read addressing (base per ks; mf/nb derived by row-step) ---
    const uint32_t r_in = ((lane >> 3) & 1) * 8 + (lane & 7);
    const uint32_t c2b  = (lane >> 4);             // 0 or 1 (16B half of k16)
    uint32_t offA0[4], offB0[4];
    #pragma unroll
    for (int ks = 0; ks < 4; ks++) {
        offA0[ks] = swz(wm * 64 + r_in, ks * 2 + c2b);
        offB0[ks] = swz(wn * 64 + r_in, ks * 2 + c2b);
    }

    auto compute_ks = [&](uint32_t Ah, int ks) {
        uint32_t Bh = Ah + TILE_B;
        uint32_t a[4][4];
        #pragma unroll
        for (int mf = 0; mf < 4; mf++)
            ldm4(a[mf], Ah + offA0[ks] + (uint32_t)mf * 16u * 128u);
        #pragma unroll
        for (int nb = 0; nb < 4; nb++) {
            uint32_t b4[4];
            ldm4(b4, Bh + offB0[ks] + (uint32_t)nb * 16u * 128u);
            #pragma unroll
            for (int mf = 0; mf < 4; mf++)
                #pragma unroll
                for (int hf = 0; hf < 2; hf++)
                    mma16816(acc[mf][nb * 2 + hf], a[mf], b4[hf], b4[2 + hf]);
        }
    };

    const uint32_t send = smem + 3u * STAGE_B;
    loads(0, smem);
    loads(1, smem + STAGE_B);
    uint32_t cs = smem;                 // stage being computed
    uint32_t ls = smem + 2u * STAGE_B;  // stage being loaded (i+2)
    for (int i = 0; i < iters; i++) {
        if (i + 1 < iters) { CP_WAIT(1); } else { CP_WAIT(0); }
        __syncthreads();
        compute_ks(cs, 0);
        compute_ks(cs, 1);
        if (i + 2 < iters) loads(i + 2, ls);
        compute_ks(cs, 2);
        compute_ks(cs, 3);
        cs += STAGE_B; if (cs == send) cs = smem;
        ls += STAGE_B; if (ls == send) ls = smem;
    }
}

// ---------------- stage 1 ----------------
// seg 0: g_Z  = sigmoid(x@Wz + h@Uz + bz)
// seg 1: g_rh = fp16( sigmoid(x@Wr + h@Ur + br) * h )
__global__ __launch_bounds__(NTHR, 2) void gru_s1(
    const float* __restrict__ hprev, const float* __restrict__ bz,
    const float* __restrict__ br)
{
    extern __shared__ char smraw[];
    uint32_t smem = smem_u32(smraw);
    const int lane = threadIdx.x & 31;
    const int wid  = threadIdx.x >> 5;
    const int wm = wid >> 1, wn = wid & 1;
    const int g = lane >> 2, tig = lane & 3;

    int seg  = blockIdx.x >> 4;          // 0 or 1
    int ncol = (blockIdx.x & 15) * BN;
    int m0   = blockIdx.y * BM;
    size_t wsz = (size_t)NK * NK;
    const __half* b1 = g_wh + (size_t)seg * wsz;          // Wz or Wr
    const __half* b2 = g_wh + (size_t)(3 + seg) * wsz;    // Uz or Ur

    float acc[4][8][4];
    #pragma unroll
    for (int i = 0; i < 4; i++)
        #pragma unroll
        for (int j = 0; j < 8; j++)
            #pragma unroll
            for (int q = 0; q < 4; q++) acc[i][j][q] = 0.0f;

    gemm_mainloop(g_xh, b1, g_hh, b2, 64, m0, ncol, smem, acc);

    #pragma unroll
    for (int mf = 0; mf < 4; mf++) {
        #pragma unroll
        for (int nf = 0; nf < 8; nf++) {
            int r0 = m0 + wm * 64 + mf * 16 + g;
            int c  = ncol + wn * 64 + nf * 8 + tig * 2;
            const float* ac = acc[mf][nf];
            size_t p0 = (size_t)r0 * NK + c;
            size_t p1 = p0 + (size_t)8 * NK;
            if (seg == 0) {
                float2 bb = *(const float2*)&bz[c];
                *(float2*)&g_Z[p0] = make_float2(sigf(ac[0] + bb.x), sigf(ac[1] + bb.y));
                *(float2*)&g_Z[p1] = make_float2(sigf(ac[2] + bb.x), sigf(ac[3] + bb.y));
            } else {
                float2 bb = *(const float2*)&br[c];
                float2 h0 = *(const float2*)&hprev[p0];
                float2 h1 = *(const float2*)&hprev[p1];
                *(uint32_t*)&g_rh[p0] = pack_h2(sigf(ac[0] + bb.x) * h0.x,
                                                sigf(ac[1] + bb.y) * h0.y);
                *(uint32_t*)&g_rh[p1] = pack_h2(sigf(ac[2] + bb.x) * h1.x,
                                                sigf(ac[3] + bb.y) * h1.y);
            }
        }
    }
}

// ---------------- stage 2 ----------------
// acc = x@Wh (pass 1) + (r*h)@Uh (pass 2);
// out = (1 - z) * h + z * tanh(acc + bh)
__global__ __launch_bounds__(NTHR, 2) void gru_s2(
    const float* __restrict__ hprev, const float* __restrict__ bh,
    float* __restrict__ out)
{
    extern __shared__ char smraw[];
    uint32_t smem = smem_u32(smraw);
    const int lane = threadIdx.x & 31;
    const int wid  = threadIdx.x >> 5;
    const int wm = wid >> 1, wn = wid & 1;
    const int g = lane >> 2, tig = lane & 3;

    int ncol = blockIdx.x * BN;
    int m0   = blockIdx.y * BM;
    size_t wsz = (size_t)NK * NK;
    const __half* wh = g_wh + (size_t)2 * wsz;   // Wh
    const __half* uh = g_wh + (size_t)5 * wsz;   // Uh

    float acc[4][8][4];
    #pragma unroll
    for (int i = 0; i < 4; i++)
        #pragma unroll
        for (int j = 0; j < 8; j++)
            #pragma unroll
            for (int q = 0; q < 4; q++) acc[i][j][q] = 0.0f;

    gemm_mainloop(g_xh, wh, g_rh, uh, 64, m0, ncol, smem, acc);

    #pragma unroll
    for (int mf = 0; mf < 4; mf++) {
        #pragma unroll
        for (int nf = 0; nf < 8; nf++) {
            int r0 = m0 + wm * 64 + mf * 16 + g;
            int c  = ncol + wn * 64 + nf * 8 + tig * 2;
            const float* ac = acc[mf][nf];
            size_t p0 = (size_t)r0 * NK + c;
            size_t p1 = p0 + (size_t)8 * NK;
            float2 bb = *(const float2*)&bh[c];
            float2 z0 = *(const float2*)&g_Z[p0];
            float2 z1 = *(const float2*)&g_Z[p1];
            float2 h0 = *(const float2*)&hprev[p0];
            float2 h1 = *(const float2*)&hprev[p1];
            float t0 = tanhf(ac[0] + bb.x);
            float t1 = tanhf(ac[1] + bb.y);
            float t2 = tanhf(ac[2] + bb.x);
            float t3 = tanhf(ac[3] + bb.y);
            *(float2*)&out[p0] = make_float2((1.0f - z0.x) * h0.x + z0.x * t0,
                                             (1.0f - z0.y) * h0.y + z0.y * t1);
            *(float2*)&out[p1] = make_float2((1.0f - z1.x) * h1.x + z1.x * t2,
                                             (1.0f - z1.y) * h1.y + z1.y * t3);
        }
    }
}

// ---------------- launch ----------------
extern "C" void kernel_launch(void* const* d_in, const int* in_sizes, int n_in,
                              void* d_out, int out_size)
{
    const float* x  = (const float*)d_in[0];
    const float* h  = (const float*)d_in[1];
    const float* Wz = (const float*)d_in[2];
    const float* Wr = (const float*)d_in[3];
    const float* Wh = (const float*)d_in[4];
    const float* Uz = (const float*)d_in[5];
    const float* Ur = (const float*)d_in[6];
    const float* Uh = (const float*)d_in[7];
    const float* bz = (const float*)d_in[8];
    const float* br = (const float*)d_in[9];
    const float* bh = (const float*)d_in[10];
    float* out = (float*)d_out;

    cudaFuncSetAttribute(gru_s1, cudaFuncAttributeMaxDynamicSharedMemorySize, SMEM_BYTES);
    cudaFuncSetAttribute(gru_s2, cudaFuncAttributeMaxDynamicSharedMemorySize, SMEM_BYTES);

    int n4blocks = (BSZ * NK / 4) / 256;                 // 16384
    cvt_half<<<dim3(n4blocks, 2), 256>>>((const float4*)x, (const float4*)h);
    wt_cvt<<<dim3(64, 64, 6), 256>>>(Wz, Wr, Wh, Uz, Ur, Uh);

    gru_s1<<<dim3(32, 64), NTHR, SMEM_BYTES>>>(h, bz, br);
    gru_s2<<<dim3(16, 64), NTHR, SMEM_BYTES>>>(h, bh, out);
}

// round 12
// speedup vs baseline: 1.0810x; 1.0810x over previous
#include <cuda_runtime.h>
#include <cuda_fp16.h>
#include <cstdint>
#include <math.h>

#define BSZ 8192
#define NK  2048
#define BM  128
#define BN  128
#define BKF 64                     // fp32 K consumed per mainloop iteration
#define TILE_B 16384               // 128 rows x 64 fp16 = 16KB (128B rows)
#define STAGE_B (2*TILE_B)         // A, B = 32KB
#define NSTAGE 3
#define SMEM_BYTES (NSTAGE*STAGE_B)   // 96KB -> 2 CTAs/SM

// ---------------- scratch (static device globals; no runtime alloc) ----------------
__device__ __half g_xh[(size_t)BSZ*NK];
__device__ __half g_hh[(size_t)BSZ*NK];
__device__ __half g_wh[(size_t)6*NK*NK];   // [w][N][K] transposed
__device__ __half g_rh[(size_t)BSZ*NK];
__device__ float  g_Z [(size_t)BSZ*NK];

// ---------------- helpers ----------------
__device__ __forceinline__ uint32_t smem_u32(const void* p) {
    uint32_t a;
    asm("{ .reg .u64 t; cvta.to.shared.u64 t, %1; cvt.u32.u64 %0, t; }" : "=r"(a) : "l"(p));
    return a;
}
__device__ __forceinline__ void cp16(uint32_t dst, const char* src) {
    asm volatile("cp.async.cg.shared.global [%0], [%1], 16;"
                 :: "r"(dst), "l"(src) : "memory");
}
#define CP_COMMIT() asm volatile("cp.async.commit_group;" ::: "memory")
#define CP_WAIT(n)  asm volatile("cp.async.wait_group %0;" :: "n"(n) : "memory")

__device__ __forceinline__ void ldm4(uint32_t* r, uint32_t addr) {
    asm volatile("ldmatrix.sync.aligned.m8n8.x4.shared.b16 {%0,%1,%2,%3}, [%4];"
                 : "=r"(r[0]), "=r"(r[1]), "=r"(r[2]), "=r"(r[3]) : "r"(addr));
}
__device__ __forceinline__ void mma16816(float* d, const uint32_t* a,
                                         uint32_t b0, uint32_t b1) {
    asm volatile(
        "mma.sync.aligned.m16n8k16.row.col.f32.f16.f16.f32 "
        "{%0,%1,%2,%3}, {%4,%5,%6,%7}, {%8,%9}, {%0,%1,%2,%3};"
        : "+f"(d[0]), "+f"(d[1]), "+f"(d[2]), "+f"(d[3])
        : "r"(a[0]), "r"(a[1]), "r"(a[2]), "r"(a[3]), "r"(b0), "r"(b1));
}
__device__ __forceinline__ float sigf(float x) { return 1.0f / (1.0f + __expf(-x)); }

__device__ __forceinline__ uint32_t pack_h2(float a, float b) {
    __half2 h = __floats2half2_rn(a, b);
    return *(uint32_t*)&h;
}

// Swizzled byte address inside a 128x64-fp16 tile (128B per row, SW128).
// row: 0..127, c: 16B-chunk index within row (0..7).
__device__ __forceinline__ uint32_t swz(uint32_t row, uint32_t c) {
    return row * 128 + ((c ^ (row & 7)) << 4);
}

// ---------------- prep: convert x and h to fp16 (one kernel) ----------------
__global__ void cvt_half(const float4* __restrict__ xin, const float4* __restrict__ hin) {
    size_t i = (size_t)blockIdx.x * 256 + threadIdx.x;   // BSZ*NK/4 threads per plane
    int which = blockIdx.y;
    const float4* in = which ? hin : xin;
    uint2* dst = (uint2*)(which ? g_hh : g_xh);
    float4 v = in[i];
    dst[i] = make_uint2(pack_h2(v.x, v.y), pack_h2(v.z, v.w));
}

// ---------------- prep: transpose + convert all 6 weights ----------------
// Tile: 64 k x 32 n.  Writes are 4B per thread, 128B contiguous per warp.
__global__ void wt_cvt(const float* __restrict__ W0, const float* __restrict__ W1,
                       const float* __restrict__ W2, const float* __restrict__ W3,
                       const float* __restrict__ W4, const float* __restrict__ W5) {
    __shared__ float t[64][33];
    int w = blockIdx.z;
    const float* src = (w == 0) ? W0 : (w == 1) ? W1 : (w == 2) ? W2
                     : (w == 3) ? W3 : (w == 4) ? W4 : W5;
    int nt = blockIdx.x * 32, kt = blockIdx.y * 64;
    int tx = threadIdx.x & 31, ty = threadIdx.x >> 5;    // ty: 0..7
    #pragma unroll
    for (int j = 0; j < 8; j++) {
        int kr = ty + j * 8;                              // 0..63
        t[kr][tx] = src[(size_t)(kt + kr) * NK + nt + tx];
    }
    __syncthreads();
    size_t wbase = (size_t)w * NK * NK;
    #pragma unroll
    for (int j = 0; j < 4; j++) {
        int rn = ty + j * 8;                              // n index 0..31
        uint32_t v = pack_h2(t[2 * tx][rn], t[2 * tx + 1][rn]);
        *(uint32_t*)&g_wh[wbase + (size_t)(nt + rn) * NK + kt + 2 * tx] = v;
    }
}

// ---------------- fp16 mma.sync mainloop (shared by both stages) ----------------
// acc += A[m0:m0+128, :] @ B[ncol:ncol+128, :]^T over `iters` chunks of 64
// fp32-K each; switches to operand set 2 at iter 32 (two-pass when iters=64).
__device__ __forceinline__ void gemm_mainloop(
    const __half* a1, const __half* b1,
    const __half* a2, const __half* b2,
    int iters, int m0, int ncol, uint32_t smem,
    float (&acc)[2][8][4])
{
    const int tid  = threadIdx.x;
    const int lane = tid & 31;
    const int wid  = tid >> 5;
    const int wm   = wid >> 1;     // 0..3
    const int wn   = wid & 1;      // 0..1

    // --- cp.async write addressing: 4 chunks per 16KB tile per thread ---
    // j-step = +32 rows => row&7 unchanged => address step is a constant.
    const uint32_t row0 = (uint32_t)tid >> 3;     // 0..31
    const uint32_t cch  = (uint32_t)tid & 7;
    const uint32_t swr0  = swz(row0, cch);
    const uint32_t offM0 = ((uint32_t)(m0 + row0) * NK + cch * 8) * 2;
    const uint32_t offN0 = ((uint32_t)(ncol + row0) * NK + cch * 8) * 2;

    // Issue half of one stage's loads (j in [jb, je)); commit handled by caller.
    auto loads_part = [&](int L, uint32_t sb, int jb, int je) {
        bool p2 = (L >= 32);
        const char* ap = (const char*)(p2 ? a2 : a1);
        const char* bp = (const char*)(p2 ? b2 : b1);
        uint32_t kk = ((uint32_t)L & 31u) * (BKF * 2);     // byte offset in K
        #pragma unroll
        for (int j = 0; j < 4; j++) {
            int jj = jb + j;
            if (jj >= je) break;
            uint32_t sw = swr0 + (uint32_t)jj * 32u * 128u;
            uint32_t go = (uint32_t)jj * 32u * NK * 2u + kk;
            cp16(sb +          sw, ap + offM0 + go);
            cp16(sb + TILE_B + sw, bp + offN0 + go);
        }
    };

    // --- ldmatrix read addressing (base per ks; mf/nb derived by row-step) ---
    const uint32_t r_in = ((lane >> 3) & 1) * 8 + (lane & 7);
    const uint32_t c2b  = (lane >> 4);             // 0 or 1 (16B half of k16)
    uint32_t offA0[4], offB0[4];
    #pragma unroll
    for (int ks = 0; ks < 4; ks++) {
        offA0[ks] = swz(wm * 32 + r_in, ks * 2 + c2b);
        offB0[ks] = swz(wn * 64 + r_in, ks * 2 + c2b);
    }

    auto compute_ks = [&](uint32_t Ah, int ks) {
        uint32_t Bh = Ah + TILE_B;
        uint32_t a[2][4];
        #pragma unroll
        for (int mf = 0; mf < 2; mf++)
            ldm4(a[mf], Ah + offA0[ks] + (uint32_t)mf * 16u * 128u);
        #pragma unroll
        for (int nb = 0; nb < 4; nb++) {
            uint32_t b4[4];
            ldm4(b4, Bh + offB0[ks] + (uint32_t)nb * 16u * 128u);
            #pragma unroll
            for (int mf = 0; mf < 2; mf++)
                #pragma unroll
                for (int hf = 0; hf < 2; hf++)
                    mma16816(acc[mf][nb * 2 + hf], a[mf], b4[hf], b4[2 + hf]);
        }
    };

    const uint32_t send = smem + 3u * STAGE_B;
    loads_part(0, smem, 0, 4); CP_COMMIT();
    loads_part(1, smem + STAGE_B, 0, 4); CP_COMMIT();
    uint32_t cs = smem;                 // stage being computed
    uint32_t ls = smem + 2u * STAGE_B;  // stage being loaded (i+2)
    for (int i = 0; i < iters; i++) {
        if (i + 1 < iters) { CP_WAIT(1); } else { CP_WAIT(0); }
        __syncthreads();
        compute_ks(cs, 0);
        if (i + 2 < iters) loads_part(i + 2, ls, 0, 2);
        compute_ks(cs, 1);
        if (i + 2 < iters) { loads_part(i + 2, ls, 2, 4); CP_COMMIT(); }
        compute_ks(cs, 2);
        compute_ks(cs, 3);
        cs += STAGE_B; if (cs == send) cs = smem;
        ls += STAGE_B; if (ls == send) ls = smem;
    }
}

// ---------------- stage 1 ----------------
// seg 0: g_Z  = sigmoid(x@Wz + h@Uz + bz)
// seg 1: g_rh = fp16( sigmoid(x@Wr + h@Ur + br) * h )
__global__ __launch_bounds__(256, 2) void gru_s1(
    const float* __restrict__ hprev, const float* __restrict__ bz,
    const float* __restrict__ br)
{
    extern __shared__ char smraw[];
    uint32_t smem = smem_u32(smraw);
    const int lane = threadIdx.x & 31;
    const int wid  = threadIdx.x >> 5;
    const int wm = wid >> 1, wn = wid & 1;
    const int g = lane >> 2, tig = lane & 3;

    int seg  = blockIdx.x >> 4;          // 0 or 1
    int ncol = (blockIdx.x & 15) * BN;
    int m0   = blockIdx.y * BM;
    size_t wsz = (size_t)NK * NK;
    const __half* b1 = g_wh + (size_t)seg * wsz;          // Wz or Wr
    const __half* b2 = g_wh + (size_t)(3 + seg) * wsz;    // Uz or Ur

    float acc[2][8][4];
    #pragma unroll
    for (int i = 0; i < 2; i++)
        #pragma unroll
        for (int j = 0; j < 8; j++)
            #pragma unroll
            for (int q = 0; q < 4; q++) acc[i][j][q] = 0.0f;

    gemm_mainloop(g_xh, b1, g_hh, b2, 64, m0, ncol, smem, acc);

    #pragma unroll
    for (int mf = 0; mf < 2; mf++) {
        #pragma unroll
        for (int nf = 0; nf < 8; nf++) {
            int r0 = m0 + wm * 32 + mf * 16 + g;
            int c  = ncol + wn * 64 + nf * 8 + tig * 2;
            const float* ac = acc[mf][nf];
            size_t p0 = (size_t)r0 * NK + c;
            size_t p1 = p0 + (size_t)8 * NK;
            if (seg == 0) {
                float2 bb = *(const float2*)&bz[c];
                *(float2*)&g_Z[p0] = make_float2(sigf(ac[0] + bb.x), sigf(ac[1] + bb.y));
                *(float2*)&g_Z[p1] = make_float2(sigf(ac[2] + bb.x), sigf(ac[3] + bb.y));
            } else {
                float2 bb = *(const float2*)&br[c];
                float2 h0 = *(const float2*)&hprev[p0];
                float2 h1 = *(const float2*)&hprev[p1];
                *(uint32_t*)&g_rh[p0] = pack_h2(sigf(ac[0] + bb.x) * h0.x,
                                                sigf(ac[1] + bb.y) * h0.y);
                *(uint32_t*)&g_rh[p1] = pack_h2(sigf(ac[2] + bb.x) * h1.x,
                                                sigf(ac[3] + bb.y) * h1.y);
            }
        }
    }
}

// ---------------- stage 2 ----------------
// acc = x@Wh (pass 1) + (r*h)@Uh (pass 2);
// out = (1 - z) * h + z * tanh(acc + bh)
__global__ __launch_bounds__(256, 2) void gru_s2(
    const float* __restrict__ hprev, const float* __restrict__ bh,
    float* __restrict__ out)
{
    extern __shared__ char smraw[];
    uint32_t smem = smem_u32(smraw);
    const int lane = threadIdx.x & 31;
    const int wid  = threadIdx.x >> 5;
    const int wm = wid >> 1, wn = wid & 1;
    const int g = lane >> 2, tig = lane & 3;

    int ncol = blockIdx.x * BN;
    int m0   = blockIdx.y * BM;
    size_t wsz = (size_t)NK * NK;
    const __half* wh = g_wh + (size_t)2 * wsz;   // Wh
    const __half* uh = g_wh + (size_t)5 * wsz;   // Uh

    float acc[2][8][4];
    #pragma unroll
    for (int i = 0; i < 2; i++)
        #pragma unroll
        for (int j = 0; j < 8; j++)
            #pragma unroll
            for (int q = 0; q < 4; q++) acc[i][j][q] = 0.0f;

    gemm_mainloop(g_xh, wh, g_rh, uh, 64, m0, ncol, smem, acc);

    #pragma unroll
    for (int mf = 0; mf < 2; mf++) {
        #pragma unroll
        for (int nf = 0; nf < 8; nf++) {
            int r0 = m0 + wm * 32 + mf * 16 + g;
            int c  = ncol + wn * 64 + nf * 8 + tig * 2;
            const float* ac = acc[mf][nf];
            size_t p0 = (size_t)r0 * NK + c;
            size_t p1 = p0 + (size_t)8 * NK;
            float2 bb = *(const float2*)&bh[c];
            float2 z0 = *(const float2*)&g_Z[p0];
            float2 z1 = *(const float2*)&g_Z[p1];
            float2 h0 = *(const float2*)&hprev[p0];
            float2 h1 = *(const float2*)&hprev[p1];
            float t0 = tanhf(ac[0] + bb.x);
            float t1 = tanhf(ac[1] + bb.y);
            float t2 = tanhf(ac[2] + bb.x);
            float t3 = tanhf(ac[3] + bb.y);
            *(float2*)&out[p0] = make_float2((1.0f - z0.x) * h0.x + z0.x * t0,
                                             (1.0f - z0.y) * h0.y + z0.y * t1);
            *(float2*)&out[p1] = make_float2((1.0f - z1.x) * h1.x + z1.x * t2,
                                             (1.0f - z1.y) * h1.y + z1.y * t3);
        }
    }
}

// ---------------- launch ----------------
extern "C" void kernel_launch(void* const* d_in, const int* in_sizes, int n_in,
                              void* d_out, int out_size)
{
    const float* x  = (const float*)d_in[0];
    const float* h  = (const float*)d_in[1];
    const float* Wz = (const float*)d_in[2];
    const float* Wr = (const float*)d_in[3];
    const float* Wh = (const float*)d_in[4];
    const float* Uz = (const float*)d_in[5];
    const float* Ur = (const float*)d_in[6];
    const float* Uh = (const float*)d_in[7];
    const float* bz = (const float*)d_in[8];
    const float* br = (const float*)d_in[9];
    const float* bh = (const float*)d_in[10];
    float* out = (float*)d_out;

    cudaFuncSetAttribute(gru_s1, cudaFuncAttributeMaxDynamicSharedMemorySize, SMEM_BYTES);
    cudaFuncSetAttribute(gru_s2, cudaFuncAttributeMaxDynamicSharedMemorySize, SMEM_BYTES);

    int n4blocks = (BSZ * NK / 4) / 256;                 // 16384
    cvt_half<<<dim3(n4blocks, 2), 256>>>((const float4*)x, (const float4*)h);
    wt_cvt<<<dim3(64, 32, 6), 256>>>(Wz, Wr, Wh, Uz, Ur, Uh);

    gru_s1<<<dim3(32, 64), 256, SMEM_BYTES>>>(h, bz, br);
    gru_s2<<<dim3(16, 64), 256, SMEM_BYTES>>>(h, bh, out);
}

// round 13
// speedup vs baseline: 1.1024x; 1.0199x over previous
#include <cuda_runtime.h>
#include <cuda_fp16.h>
#include <cstdint>
#include <math.h>

#define BSZ 8192
#define NK  2048
#define BM  128
#define BN  128
#define BKF 64                     // fp32 K consumed per mainloop iteration
#define TILE_B 16384               // 128 rows x 64 fp16 = 16KB (128B rows)
#define STAGE_B (2*TILE_B)         // A, B = 32KB
#define NSTAGE 3
#define SMEM_BYTES (NSTAGE*STAGE_B)   // 96KB -> 2 CTAs/SM

// ---------------- scratch (static device globals; no runtime alloc) ----------------
__device__ __half g_xh[(size_t)BSZ*NK];
__device__ __half g_hh[(size_t)BSZ*NK];
__device__ __half g_wh[(size_t)6*NK*NK];   // [w][N][K] transposed
__device__ __half g_rh[(size_t)BSZ*NK];
__device__ float  g_Z [(size_t)BSZ*NK];

// ---------------- helpers ----------------
__device__ __forceinline__ uint32_t smem_u32(const void* p) {
    uint32_t a;
    asm("{ .reg .u64 t; cvta.to.shared.u64 t, %1; cvt.u32.u64 %0, t; }" : "=r"(a) : "l"(p));
    return a;
}
__device__ __forceinline__ void cp16(uint32_t dst, const char* src) {
    asm volatile("cp.async.cg.shared.global [%0], [%1], 16;"
                 :: "r"(dst), "l"(src) : "memory");
}
#define CP_COMMIT() asm volatile("cp.async.commit_group;" ::: "memory")
#define CP_WAIT(n)  asm volatile("cp.async.wait_group %0;" :: "n"(n) : "memory")

__device__ __forceinline__ void ldm4(uint32_t* r, uint32_t addr) {
    asm volatile("ldmatrix.sync.aligned.m8n8.x4.shared.b16 {%0,%1,%2,%3}, [%4];"
                 : "=r"(r[0]), "=r"(r[1]), "=r"(r[2]), "=r"(r[3]) : "r"(addr));
}
__device__ __forceinline__ void mma16816(float* d, const uint32_t* a,
                                         uint32_t b0, uint32_t b1) {
    asm volatile(
        "mma.sync.aligned.m16n8k16.row.col.f32.f16.f16.f32 "
        "{%0,%1,%2,%3}, {%4,%5,%6,%7}, {%8,%9}, {%0,%1,%2,%3};"
        : "+f"(d[0]), "+f"(d[1]), "+f"(d[2]), "+f"(d[3])
        : "r"(a[0]), "r"(a[1]), "r"(a[2]), "r"(a[3]), "r"(b0), "r"(b1));
}
__device__ __forceinline__ float sigf(float x) { return 1.0f / (1.0f + __expf(-x)); }

__device__ __forceinline__ uint32_t pack_h2(float a, float b) {
    __half2 h = __floats2half2_rn(a, b);
    return *(uint32_t*)&h;
}

// Swizzled byte address inside a 128x64-fp16 tile (128B per row, SW128).
// row: 0..127, c: 16B-chunk index within row (0..7).
__device__ __forceinline__ uint32_t swz(uint32_t row, uint32_t c) {
    return row * 128 + ((c ^ (row & 7)) << 4);
}

// ---------------- prep: convert x and h to fp16 (one kernel) ----------------
__global__ void cvt_half(const float4* __restrict__ xin, const float4* __restrict__ hin) {
    size_t i = (size_t)blockIdx.x * 256 + threadIdx.x;   // BSZ*NK/4 threads per plane
    int which = blockIdx.y;
    const float4* in = which ? hin : xin;
    uint2* dst = (uint2*)(which ? g_hh : g_xh);
    float4 v = in[i];
    dst[i] = make_uint2(pack_h2(v.x, v.y), pack_h2(v.z, v.w));
}

// ---------------- prep: transpose + convert all 6 weights ----------------
// Tile: 64 k x 32 n.  Writes are 4B per thread, 128B contiguous per warp.
__global__ void wt_cvt(const float* __restrict__ W0, const float* __restrict__ W1,
                       const float* __restrict__ W2, const float* __restrict__ W3,
                       const float* __restrict__ W4, const float* __restrict__ W5) {
    __shared__ float t[64][33];
    int w = blockIdx.z;
    const float* src = (w == 0) ? W0 : (w == 1) ? W1 : (w == 2) ? W2
                     : (w == 3) ? W3 : (w == 4) ? W4 : W5;
    int nt = blockIdx.x * 32, kt = blockIdx.y * 64;
    int tx = threadIdx.x & 31, ty = threadIdx.x >> 5;    // ty: 0..7
    #pragma unroll
    for (int j = 0; j < 8; j++) {
        int kr = ty + j * 8;                              // 0..63
        t[kr][tx] = src[(size_t)(kt + kr) * NK + nt + tx];
    }
    __syncthreads();
    size_t wbase = (size_t)w * NK * NK;
    #pragma unroll
    for (int j = 0; j < 4; j++) {
        int rn = ty + j * 8;                              // n index 0..31
        uint32_t v = pack_h2(t[2 * tx][rn], t[2 * tx + 1][rn]);
        *(uint32_t*)&g_wh[wbase + (size_t)(nt + rn) * NK + kt + 2 * tx] = v;
    }
}

// ---------------- fp16 mma.sync mainloop (shared by both stages) ----------------
// acc += A[m0:m0+128, :] @ B[ncol:ncol+128, :]^T over `iters` chunks of 64
// fp32-K each; switches to operand set 2 at iter 32 (two-pass when iters=64).
__device__ __forceinline__ void gemm_mainloop(
    const __half* a1, const __half* b1,
    const __half* a2, const __half* b2,
    int iters, int m0, int ncol, uint32_t smem,
    float (&acc)[2][8][4])
{
    const int tid  = threadIdx.x;
    const int lane = tid & 31;
    const int wid  = tid >> 5;
    const int wm   = wid >> 1;     // 0..3
    const int wn   = wid & 1;      // 0..1

    // --- cp.async write addressing: 4 chunks per 16KB tile per thread ---
    // j-step = +32 rows => row&7 unchanged => address step is a constant.
    const uint32_t row0 = (uint32_t)tid >> 3;     // 0..31
    const uint32_t cch  = (uint32_t)tid & 7;
    const uint32_t swr0  = swz(row0, cch);
    const uint32_t offM0 = ((uint32_t)(m0 + row0) * NK + cch * 8) * 2;
    const uint32_t offN0 = ((uint32_t)(ncol + row0) * NK + cch * 8) * 2;

    auto loads = [&](int L, uint32_t sb) {
        bool p2 = (L >= 32);
        const char* ap = (const char*)(p2 ? a2 : a1);
        const char* bp = (const char*)(p2 ? b2 : b1);
        uint32_t kk = ((uint32_t)L & 31u) * (BKF * 2);     // byte offset in K
        #pragma unroll
        for (int j = 0; j < 4; j++) {
            uint32_t sw = swr0 + (uint32_t)j * 32u * 128u;
            uint32_t go = (uint32_t)j * 32u * NK * 2u + kk;
            cp16(sb +          sw, ap + offM0 + go);
            cp16(sb + TILE_B + sw, bp + offN0 + go);
        }
        CP_COMMIT();
    };

    // --- ldmatrix read addressing (base per ks; mf/nb derived by row-step) ---
    const uint32_t r_in = ((lane >> 3) & 1) * 8 + (lane & 7);
    const uint32_t c2b  = (lane >> 4);             // 0 or 1 (16B half of k16)
    uint32_t offA0[4], offB0[4];
    #pragma unroll
    for (int ks = 0; ks < 4; ks++) {
        offA0[ks] = swz(wm * 32 + r_in, ks * 2 + c2b);
        offB0[ks] = swz(wn * 64 + r_in, ks * 2 + c2b);
    }

    auto compute_ks = [&](uint32_t Ah, int ks) {
        uint32_t Bh = Ah + TILE_B;
        uint32_t a[2][4];
        #pragma unroll
        for (int mf = 0; mf < 2; mf++)
            ldm4(a[mf], Ah + offA0[ks] + (uint32_t)mf * 16u * 128u);
        #pragma unroll
        for (int nb = 0; nb < 4; nb++) {
            uint32_t b4[4];
            ldm4(b4, Bh + offB0[ks] + (uint32_t)nb * 16u * 128u);
            #pragma unroll
            for (int mf = 0; mf < 2; mf++)
                #pragma unroll
                for (int hf = 0; hf < 2; hf++)
                    mma16816(acc[mf][nb * 2 + hf], a[mf], b4[hf], b4[2 + hf]);
        }
    };

    const uint32_t send = smem + 3u * STAGE_B;
    loads(0, smem);
    loads(1, smem + STAGE_B);
    uint32_t cs = smem;                 // stage being computed
    uint32_t ls = smem + 2u * STAGE_B;  // stage being loaded (i+2)
    for (int i = 0; i < iters; i++) {
        if (i + 1 < iters) { CP_WAIT(1); } else { CP_WAIT(0); }
        __syncthreads();
        compute_ks(cs, 0);
        compute_ks(cs, 1);
        if (i + 2 < iters) loads(i + 2, ls);
        compute_ks(cs, 2);
        compute_ks(cs, 3);
        cs += STAGE_B; if (cs == send) cs = smem;
        ls += STAGE_B; if (ls == send) ls = smem;
    }
}

// ---------------- stage 1 ----------------
// seg 0: g_Z  = sigmoid(x@Wz + h@Uz + bz)
// seg 1: g_rh = fp16( sigmoid(x@Wr + h@Ur + br) * h )
__global__ __launch_bounds__(256, 2) void gru_s1(
    const float* __restrict__ hprev, const float* __restrict__ bz,
    const float* __restrict__ br)
{
    extern __shared__ char smraw[];
    uint32_t smem = smem_u32(smraw);
    const int lane = threadIdx.x & 31;
    const int wid  = threadIdx.x >> 5;
    const int wm = wid >> 1, wn = wid & 1;
    const int g = lane >> 2, tig = lane & 3;

    int seg  = blockIdx.x >> 4;          // 0 or 1
    int ncol = (blockIdx.x & 15) * BN;
    int m0   = blockIdx.y * BM;
    size_t wsz = (size_t)NK * NK;
    const __half* b1 = g_wh + (size_t)seg * wsz;          // Wz or Wr
    const __half* b2 = g_wh + (size_t)(3 + seg) * wsz;    // Uz or Ur

    float acc[2][8][4];
    #pragma unroll
    for (int i = 0; i < 2; i++)
        #pragma unroll
        for (int j = 0; j < 8; j++)
            #pragma unroll
            for (int q = 0; q < 4; q++) acc[i][j][q] = 0.0f;

    gemm_mainloop(g_xh, b1, g_hh, b2, 64, m0, ncol, smem, acc);

    #pragma unroll
    for (int mf = 0; mf < 2; mf++) {
        #pragma unroll
        for (int nf = 0; nf < 8; nf++) {
            int r0 = m0 + wm * 32 + mf * 16 + g;
            int c  = ncol + wn * 64 + nf * 8 + tig * 2;
            const float* ac = acc[mf][nf];
            size_t p0 = (size_t)r0 * NK + c;
            size_t p1 = p0 + (size_t)8 * NK;
            if (seg == 0) {
                float2 bb = *(const float2*)&bz[c];
                *(float2*)&g_Z[p0] = make_float2(sigf(ac[0] + bb.x), sigf(ac[1] + bb.y));
                *(float2*)&g_Z[p1] = make_float2(sigf(ac[2] + bb.x), sigf(ac[3] + bb.y));
            } else {
                float2 bb = *(const float2*)&br[c];
                float2 h0 = *(const float2*)&hprev[p0];
                float2 h1 = *(const float2*)&hprev[p1];
                *(uint32_t*)&g_rh[p0] = pack_h2(sigf(ac[0] + bb.x) * h0.x,
                                                sigf(ac[1] + bb.y) * h0.y);
                *(uint32_t*)&g_rh[p1] = pack_h2(sigf(ac[2] + bb.x) * h1.x,
                                                sigf(ac[3] + bb.y) * h1.y);
            }
        }
    }
}

// ---------------- stage 2 ----------------
// acc = x@Wh (pass 1) + (r*h)@Uh (pass 2);
// out = (1 - z) * h + z * tanh(acc + bh)
__global__ __launch_bounds__(256, 2) void gru_s2(
    const float* __restrict__ hprev, const float* __restrict__ bh,
    float* __restrict__ out)
{
    extern __shared__ char smraw[];
    uint32_t smem = smem_u32(smraw);
    const int lane = threadIdx.x & 31;
    const int wid  = threadIdx.x >> 5;
    const int wm = wid >> 1, wn = wid & 1;
    const int g = lane >> 2, tig = lane & 3;

    int ncol = blockIdx.x * BN;
    int m0   = blockIdx.y * BM;
    size_t wsz = (size_t)NK * NK;
    const __half* wh = g_wh + (size_t)2 * wsz;   // Wh
    const __half* uh = g_wh + (size_t)5 * wsz;   // Uh

    float acc[2][8][4];
    #pragma unroll
    for (int i = 0; i < 2; i++)
        #pragma unroll
        for (int j = 0; j < 8; j++)
            #pragma unroll
            for (int q = 0; q < 4; q++) acc[i][j][q] = 0.0f;

    gemm_mainloop(g_xh, wh, g_rh, uh, 64, m0, ncol, smem, acc);

    #pragma unroll
    for (int mf = 0; mf < 2; mf++) {
        #pragma unroll
        for (int nf = 0; nf < 8; nf++) {
            int r0 = m0 + wm * 32 + mf * 16 + g;
            int c  = ncol + wn * 64 + nf * 8 + tig * 2;
            const float* ac = acc[mf][nf];
            size_t p0 = (size_t)r0 * NK + c;
            size_t p1 = p0 + (size_t)8 * NK;
            float2 bb = *(const float2*)&bh[c];
            float2 z0 = *(const float2*)&g_Z[p0];
            float2 z1 = *(const float2*)&g_Z[p1];
            float2 h0 = *(const float2*)&hprev[p0];
            float2 h1 = *(const float2*)&hprev[p1];
            float t0 = tanhf(ac[0] + bb.x);
            float t1 = tanhf(ac[1] + bb.y);
            float t2 = tanhf(ac[2] + bb.x);
            float t3 = tanhf(ac[3] + bb.y);
            *(float2*)&out[p0] = make_float2((1.0f - z0.x) * h0.x + z0.x * t0,
                                             (1.0f - z0.y) * h0.y + z0.y * t1);
            *(float2*)&out[p1] = make_float2((1.0f - z1.x) * h1.x + z1.x * t2,
                                             (1.0f - z1.y) * h1.y + z1.y * t3);
        }
    }
}

// ---------------- launch ----------------
extern "C" void kernel_launch(void* const* d_in, const int* in_sizes, int n_in,
                              void* d_out, int out_size)
{
    const float* x  = (const float*)d_in[0];
    const float* h  = (const float*)d_in[1];
    const float* Wz = (const float*)d_in[2];
    const float* Wr = (const float*)d_in[3];
    const float* Wh = (const float*)d_in[4];
    const float* Uz = (const float*)d_in[5];
    const float* Ur = (const float*)d_in[6];
    const float* Uh = (const float*)d_in[7];
    const float* bz = (const float*)d_in[8];
    const float* br = (const float*)d_in[9];
    const float* bh = (const float*)d_in[10];
    float* out = (float*)d_out;

    cudaFuncSetAttribute(gru_s1, cudaFuncAttributeMaxDynamicSharedMemorySize, SMEM_BYTES);
    cudaFuncSetAttribute(gru_s2, cudaFuncAttributeMaxDynamicSharedMemorySize, SMEM_BYTES);

    int n4blocks = (BSZ * NK / 4) / 256;                 // 16384
    cvt_half<<<dim3(n4blocks, 2), 256>>>((const float4*)x, (const float4*)h);
    wt_cvt<<<dim3(64, 32, 6), 256>>>(Wz, Wr, Wh, Uz, Ur, Uh);

    gru_s1<<<dim3(32, 64), 256, SMEM_BYTES>>>(h, bz, br);
    gru_s2<<<dim3(16, 64), 256, SMEM_BYTES>>>(h, bh, out);
}